// round 1
// baseline (speedup 1.0000x reference)
#include <cuda_runtime.h>
#include <cuda_bf16.h>

// Problem constants
#define NN   32768
#define FIN  128
#define CC   256
#define HH   4
#define FH   64
#define EE   524288
#define BB   64
#define NPG  512
#define K1   256
#define K2   128

// ---------------- scratch (device globals; no allocation allowed) ----------
__device__ float    g_hlin[NN * CC];        // h = x@W (pre-attention features)
__device__ float    g_hout[NN * CC];        // GAT output / next-layer input
__device__ float    g_es[NN * HH];
__device__ float    g_ed[NN * HH];
__device__ float    g_eself[NN * HH];
__device__ float    g_m[NN * HH];
__device__ float    g_den[NN * HH];
__device__ unsigned g_menc[NN * HH];
__device__ float    g_ex[EE * HH];
__device__ float    g_sel[(BB * K1) * CC];  // gather buffer (reused for pool2)
__device__ float    g_pool1[(BB * K1) * CC];
__device__ float    g_pool2[(BB * K2) * CC];
__device__ int      g_idx[BB * K1];
__device__ float    g_scores[NN];
__device__ float    g_gmean[BB * CC];
__device__ float    g_fc1[BB * 64];

// ---------------- SGEMM: C[M,N] = A[M,K] @ B[K,N] (+bias), fp32 ------------
// 64x64 tile, 256 threads, 4x4 per thread, BK=16. M%64==0, N%64==0, K%16==0.
__global__ void sgemm64(const float* __restrict__ A, const float* __restrict__ Bm,
                        const float* __restrict__ bias, float* __restrict__ Cm,
                        int M, int N, int K) {
    __shared__ float As[16][64];
    __shared__ float Bs[16][64];
    const int tid = threadIdx.x;
    const int tx = tid & 15, ty = tid >> 4;
    const int row0 = blockIdx.y * 64;
    const int col0 = blockIdx.x * 64;
    const int arow = tid >> 2, acol4 = (tid & 3) * 4;
    const int brow = tid >> 4, bcol4 = (tid & 15) * 4;
    float acc[4][4] = {};
    for (int k0 = 0; k0 < K; k0 += 16) {
        float4 av = *reinterpret_cast<const float4*>(&A[(size_t)(row0 + arow) * K + k0 + acol4]);
        As[acol4 + 0][arow] = av.x; As[acol4 + 1][arow] = av.y;
        As[acol4 + 2][arow] = av.z; As[acol4 + 3][arow] = av.w;
        float4 bv = *reinterpret_cast<const float4*>(&Bm[(size_t)(k0 + brow) * N + col0 + bcol4]);
        *reinterpret_cast<float4*>(&Bs[brow][bcol4]) = bv;
        __syncthreads();
#pragma unroll
        for (int kk = 0; kk < 16; kk++) {
            float4 a4 = *reinterpret_cast<const float4*>(&As[kk][ty * 4]);
            float4 b4 = *reinterpret_cast<const float4*>(&Bs[kk][tx * 4]);
            float a[4] = {a4.x, a4.y, a4.z, a4.w};
            float b[4] = {b4.x, b4.y, b4.z, b4.w};
#pragma unroll
            for (int i = 0; i < 4; i++)
#pragma unroll
                for (int j = 0; j < 4; j++) acc[i][j] += a[i] * b[j];
        }
        __syncthreads();
    }
#pragma unroll
    for (int i = 0; i < 4; i++) {
        const int r = row0 + ty * 4 + i;
#pragma unroll
        for (int j = 0; j < 4; j++) {
            const int c = col0 + tx * 4 + j;
            float v = acc[i][j];
            if (bias) v += bias[c];
            Cm[(size_t)r * N + c] = v;
        }
    }
}

// ---------------- attention logits: es/ed per (node, head) -----------------
__global__ void esed_kernel(const float* __restrict__ hlin,
                            const float* __restrict__ a_src,
                            const float* __restrict__ a_dst,
                            float* __restrict__ es, float* __restrict__ ed) {
    const int w = (blockIdx.x * blockDim.x + threadIdx.x) >> 5;  // (n*H+h)
    const int lane = threadIdx.x & 31;
    if (w >= NN * HH) return;
    const int n = w >> 2, h = w & 3;
    const float* hp = hlin + (size_t)n * CC + h * FH;
    const float v0 = hp[lane], v1 = hp[lane + 32];
    float s = v0 * a_src[h * FH + lane] + v1 * a_src[h * FH + lane + 32];
    float d = v0 * a_dst[h * FH + lane] + v1 * a_dst[h * FH + lane + 32];
#pragma unroll
    for (int o = 16; o; o >>= 1) {
        s += __shfl_xor_sync(0xffffffffu, s, o);
        d += __shfl_xor_sync(0xffffffffu, d, o);
    }
    if (lane == 0) { es[w] = s; ed[w] = d; }
}

__device__ __forceinline__ unsigned enc_f(float f) {
    unsigned u = __float_as_uint(f);
    return (u & 0x80000000u) ? ~u : (u | 0x80000000u);
}
__device__ __forceinline__ float dec_f(unsigned u) {
    return __uint_as_float((u & 0x80000000u) ? (u ^ 0x80000000u) : ~u);
}
__device__ __forceinline__ float leaky(float x) { return x > 0.f ? x : 0.2f * x; }

__global__ void att_init(const float* __restrict__ es, const float* __restrict__ ed,
                         float* __restrict__ eself, unsigned* __restrict__ menc) {
    const int i = blockIdx.x * blockDim.x + threadIdx.x;
    if (i >= NN * HH) return;
    const float e = leaky(es[i] + ed[i]);  // self-loop logit
    eself[i] = e;
    menc[i] = enc_f(e);
}

__global__ void edge_max(const int* __restrict__ ei, const float* __restrict__ es,
                         const float* __restrict__ ed, unsigned* __restrict__ menc) {
    const int e = blockIdx.x * blockDim.x + threadIdx.x;
    if (e >= EE) return;
    const int s = ei[e], d = ei[EE + e];
#pragma unroll
    for (int h = 0; h < HH; h++) {
        const float v = leaky(es[s * HH + h] + ed[d * HH + h]);
        atomicMax(&menc[d * HH + h], enc_f(v));
    }
}

__global__ void den_init(const unsigned* __restrict__ menc, const float* __restrict__ eself,
                         float* __restrict__ m, float* __restrict__ den) {
    const int i = blockIdx.x * blockDim.x + threadIdx.x;
    if (i >= NN * HH) return;
    const float mv = dec_f(menc[i]);
    m[i] = mv;
    den[i] = __expf(eself[i] - mv);
}

__global__ void edge_exp(const int* __restrict__ ei, const float* __restrict__ es,
                         const float* __restrict__ ed, const float* __restrict__ m,
                         float* __restrict__ ex, float* __restrict__ den) {
    const int e = blockIdx.x * blockDim.x + threadIdx.x;
    if (e >= EE) return;
    const int s = ei[e], d = ei[EE + e];
#pragma unroll
    for (int h = 0; h < HH; h++) {
        const float v = leaky(es[s * HH + h] + ed[d * HH + h]);
        const float t = __expf(v - m[d * HH + h]);
        ex[e * HH + h] = t;
        atomicAdd(&den[d * HH + h], t);
    }
}

// out[n] = alpha_self * h[n] + bias   (vectorized float4: N*64 threads)
__global__ void agg_init(const float* __restrict__ hlin, const float* __restrict__ eself,
                         const float* __restrict__ m, const float* __restrict__ den,
                         const float* __restrict__ bias, float* __restrict__ out) {
    const int idx = blockIdx.x * blockDim.x + threadIdx.x;
    if (idx >= NN * 64) return;
    const int n = idx >> 6, c4 = idx & 63;
    const int h = c4 >> 4;
    const float a = __expf(eself[n * HH + h] - m[n * HH + h]) / (den[n * HH + h] + 1e-16f);
    const float4 hv = *reinterpret_cast<const float4*>(&hlin[(size_t)n * CC + c4 * 4]);
    const float4 bv = *reinterpret_cast<const float4*>(&bias[c4 * 4]);
    float4 o;
    o.x = a * hv.x + bv.x; o.y = a * hv.y + bv.y;
    o.z = a * hv.z + bv.z; o.w = a * hv.w + bv.w;
    *reinterpret_cast<float4*>(&out[(size_t)n * CC + c4 * 4]) = o;
}

// warp per edge: out[d] += alpha * h[s]
__global__ void edge_agg(const int* __restrict__ ei, const float* __restrict__ ex,
                         const float* __restrict__ den, const float* __restrict__ hlin,
                         float* __restrict__ out) {
    const int w = (blockIdx.x * blockDim.x + threadIdx.x) >> 5;
    const int lane = threadIdx.x & 31;
    if (w >= EE) return;
    const int s = ei[w], d = ei[EE + w];
    const float* hs = hlin + (size_t)s * CC;
    float* od = out + (size_t)d * CC;
    float alpha = 0.f;
#pragma unroll
    for (int j = 0; j < 8; j++) {
        if ((j & 1) == 0) {
            const int h = j >> 1;
            alpha = ex[w * HH + h] / (den[d * HH + h] + 1e-16f);
        }
        const int c = lane + 32 * j;
        atomicAdd(&od[c], alpha * hs[c]);
    }
}

__global__ void elu_kernel(float* __restrict__ x, int n4) {
    const int i = blockIdx.x * blockDim.x + threadIdx.x;
    if (i >= n4) return;
    float4 v = reinterpret_cast<float4*>(x)[i];
    v.x = v.x > 0.f ? v.x : (__expf(v.x) - 1.f);
    v.y = v.y > 0.f ? v.y : (__expf(v.y) - 1.f);
    v.z = v.z > 0.f ? v.z : (__expf(v.z) - 1.f);
    v.w = v.w > 0.f ? v.w : (__expf(v.w) - 1.f);
    reinterpret_cast<float4*>(x)[i] = v;
}

// ---------------- pooling ---------------------------------------------------
__global__ void score_kernel(const float* __restrict__ X, const float* __restrict__ sw,
                             const float* __restrict__ sb, float* __restrict__ scores,
                             int rows) {
    const int w = (blockIdx.x * blockDim.x + threadIdx.x) >> 5;
    const int lane = threadIdx.x & 31;
    if (w >= rows) return;
    float s = 0.f;
#pragma unroll
    for (int c = lane; c < CC; c += 32) s += X[(size_t)w * CC + c] * sw[c];
#pragma unroll
    for (int o = 16; o; o >>= 1) s += __shfl_xor_sync(0xffffffffu, s, o);
    if (lane == 0) scores[w] = 1.f / (1.f + __expf(-(s + sb[0])));
}

template <int NPB, int KSEL>
__global__ void topk_kernel(const float* __restrict__ scores, int* __restrict__ idx_out) {
    __shared__ float sv[NPB];
    __shared__ int si[NPB];
    const int b = blockIdx.x, t = threadIdx.x;
    sv[t] = scores[b * NPB + t];
    si[t] = t;
    __syncthreads();
    for (int k = 2; k <= NPB; k <<= 1) {
        for (int j = k >> 1; j > 0; j >>= 1) {
            const int ixj = t ^ j;
            if (ixj > t) {
                const bool desc = ((t & k) == 0);
                const float a = sv[t], c = sv[ixj];
                if ((a < c) == desc) {
                    sv[t] = c; sv[ixj] = a;
                    const int tmp = si[t]; si[t] = si[ixj]; si[ixj] = tmp;
                }
            }
            __syncthreads();
        }
    }
    if (t < KSEL) idx_out[b * KSEL + t] = b * NPB + si[t];
}

__global__ void gather_kernel(const float* __restrict__ X, const int* __restrict__ idx,
                              float* __restrict__ out, int rows) {
    const int g = blockIdx.x * blockDim.x + threadIdx.x;
    if (g >= rows * 64) return;
    const int r = g >> 6, c4 = (g & 63) * 4;
    const float4 v = *reinterpret_cast<const float4*>(&X[(size_t)idx[r] * CC + c4]);
    *reinterpret_cast<float4*>(&out[(size_t)r * CC + c4]) = v;
}

// ---------------- readout ---------------------------------------------------
__global__ void mean_kernel(const float* __restrict__ X, float* __restrict__ g) {
    const int i = blockIdx.x * blockDim.x + threadIdx.x;
    if (i >= BB * CC) return;
    const int b = i >> 8, c = i & 255;
    float s = 0.f;
    for (int r = 0; r < K2; r++) s += X[(size_t)(b * K2 + r) * CC + c];
    g[i] = s * (1.f / K2);
}

__global__ void fc1_kernel(const float* __restrict__ g, const float* __restrict__ w,
                           const float* __restrict__ bias, float* __restrict__ out) {
    const int i = blockIdx.x * blockDim.x + threadIdx.x;
    if (i >= BB * 64) return;
    const int b = i >> 6, o = i & 63;
    float s = bias[o];
    for (int k = 0; k < CC; k++) s += g[b * CC + k] * w[k * 64 + o];
    out[i] = s > 0.f ? s : 0.f;
}

__global__ void fc2_lsm_kernel(const float* __restrict__ f, const float* __restrict__ w,
                               const float* __restrict__ bias, float* __restrict__ out) {
    const int b = threadIdx.x;
    if (b >= BB) return;
    float l0 = bias[0], l1 = bias[1];
    for (int k = 0; k < 64; k++) {
        const float v = f[b * 64 + k];
        l0 += v * w[k * 2 + 0];
        l1 += v * w[k * 2 + 1];
    }
    const float mm = fmaxf(l0, l1);
    const float lse = mm + logf(__expf(l0 - mm) + __expf(l1 - mm));
    out[b * 2 + 0] = l0 - lse;
    out[b * 2 + 1] = l1 - lse;
}

// ---------------- host orchestration ----------------------------------------
static float* sym(const void* s) {
    void* p = nullptr;
    cudaGetSymbolAddress(&p, (const void*)s);
    return (float*)p;
}

static void run_gat_tail(const int* ei, const float* asrc, const float* adst,
                         const float* bias, float* hlin, float* hout,
                         float* es, float* ed, float* eself, float* m, float* den,
                         unsigned* menc, float* ex) {
    esed_kernel<<<(NN * HH) / 8, 256>>>(hlin, asrc, adst, es, ed);
    att_init<<<(NN * HH) / 256, 256>>>(es, ed, eself, menc);
    edge_max<<<EE / 256, 256>>>(ei, es, ed, menc);
    den_init<<<(NN * HH) / 256, 256>>>(menc, eself, m, den);
    edge_exp<<<EE / 256, 256>>>(ei, es, ed, m, ex, den);
    agg_init<<<(NN * 64) / 256, 256>>>(hlin, eself, m, den, bias, hout);
    edge_agg<<<(EE * 32) / 256, 256>>>(ei, ex, den, hlin, hout);
    elu_kernel<<<(NN * CC / 4) / 256, 256>>>(hout, NN * CC / 4);
}

extern "C" void kernel_launch(void* const* d_in, const int* in_sizes, int n_in,
                              void* d_out, int out_size) {
    const float* x      = (const float*)d_in[0];
    const int*   ei     = (const int*)  d_in[1];
    const float* W1     = (const float*)d_in[3];
    const float* asrc1  = (const float*)d_in[4];
    const float* adst1  = (const float*)d_in[5];
    const float* b1     = (const float*)d_in[6];
    const float* W2     = (const float*)d_in[7];
    const float* asrc2  = (const float*)d_in[8];
    const float* adst2  = (const float*)d_in[9];
    const float* b2     = (const float*)d_in[10];
    const float* p1_sw  = (const float*)d_in[11];
    const float* p1_sb  = (const float*)d_in[12];
    const float* p1_tw  = (const float*)d_in[13];
    const float* p1_tb  = (const float*)d_in[14];
    const float* p2_sw  = (const float*)d_in[15];
    const float* p2_sb  = (const float*)d_in[16];
    const float* p2_tw  = (const float*)d_in[17];
    const float* p2_tb  = (const float*)d_in[18];
    const float* c1w    = (const float*)d_in[19];
    const float* c1b    = (const float*)d_in[20];
    const float* c2w    = (const float*)d_in[21];
    const float* c2b    = (const float*)d_in[22];
    float* out = (float*)d_out;

    float*    hlin  = sym(g_hlin);
    float*    hout  = sym(g_hout);
    float*    es    = sym(g_es);
    float*    ed    = sym(g_ed);
    float*    eself = sym(g_eself);
    float*    m     = sym(g_m);
    float*    den   = sym(g_den);
    unsigned* menc  = (unsigned*)sym(g_menc);
    float*    ex    = sym(g_ex);
    float*    selb  = sym(g_sel);
    float*    pool1 = sym(g_pool1);
    float*    pool2 = sym(g_pool2);
    int*      idx   = (int*)sym(g_idx);
    float*    sc    = sym(g_scores);
    float*    gmean = sym(g_gmean);
    float*    fc1   = sym(g_fc1);

    dim3 t256(256);

    // ---- GAT layer 1 ----
    sgemm64<<<dim3(CC / 64, NN / 64), t256>>>(x, W1, nullptr, hlin, NN, CC, FIN);
    run_gat_tail(ei, asrc1, adst1, b1, hlin, hout, es, ed, eself, m, den, menc, ex);

    // ---- GAT layer 2 ----
    sgemm64<<<dim3(CC / 64, NN / 64), t256>>>(hout, W2, nullptr, hlin, NN, CC, CC);
    run_gat_tail(ei, asrc2, adst2, b2, hlin, hout, es, ed, eself, m, den, menc, ex);

    // ---- Pool 1 (top-256 of 512 per graph) ----
    score_kernel<<<(NN * 32) / 256, t256>>>(hout, p1_sw, p1_sb, sc, NN);
    topk_kernel<NPG, K1><<<BB, NPG>>>(sc, idx);
    gather_kernel<<<(BB * K1 * 64) / 256, t256>>>(hout, idx, selb, BB * K1);
    sgemm64<<<dim3(CC / 64, (BB * K1) / 64), t256>>>(selb, p1_tw, p1_tb, pool1, BB * K1, CC, CC);

    // ---- Pool 2 (top-128 of 256 per graph) ----
    score_kernel<<<(BB * K1 * 32) / 256, t256>>>(pool1, p2_sw, p2_sb, sc, BB * K1);
    topk_kernel<K1, K2><<<BB, K1>>>(sc, idx);
    gather_kernel<<<(BB * K2 * 64) / 256, t256>>>(pool1, idx, selb, BB * K2);
    sgemm64<<<dim3(CC / 64, (BB * K2) / 64), t256>>>(selb, p2_tw, p2_tb, pool2, BB * K2, CC, CC);

    // ---- readout ----
    mean_kernel<<<(BB * CC) / 256, t256>>>(pool2, gmean);
    fc1_kernel<<<(BB * 64) / 256, t256>>>(gmean, c1w, c1b, fc1);
    fc2_lsm_kernel<<<1, 64>>>(fc1, c2w, c2b, out);
}

// round 2
// speedup vs baseline: 1.2675x; 1.2675x over previous
#include <cuda_runtime.h>
#include <cuda_bf16.h>

// Problem constants
#define NN   32768
#define FIN  128
#define CC   256
#define HH   4
#define FH   64
#define EE   524288
#define BB   64
#define NPG  512
#define K1   256
#define K2   128

// ---------------- scratch (device globals; no allocation allowed) ----------
__device__ float    g_hlin[NN * CC];        // h = x@W (pre-attention features)
__device__ float    g_hout[NN * CC];        // GAT output / next-layer input
__device__ float    g_es[NN * HH];
__device__ float    g_ed[NN * HH];
__device__ float    g_dinv[NN * HH];        // 1/(den+eps) per (node, head)
__device__ float    g_aself[NN * HH];       // alpha_self premultiplied
__device__ float    g_ex[EE * HH];          // CSR-ordered e / ex values
__device__ int      g_deg[NN];
__device__ int      g_off[NN + 1];
__device__ int      g_cur[NN];
__device__ int      g_csrc[EE];
__device__ float    g_sel[(BB * K1) * CC];
__device__ float    g_pool1[(BB * K1) * CC];
__device__ float    g_pool2[(BB * K2) * CC];
__device__ int      g_idx[BB * K1];
__device__ float    g_scores[NN];
__device__ float    g_gmean[BB * CC];
__device__ float    g_fc1[BB * 64];

__device__ __forceinline__ float leaky(float x) { return x > 0.f ? x : 0.2f * x; }

// ---------------- SGEMM: C[M,N] = A[M,K] @ B[K,N] (+bias), fp32 ------------
// 128x128 tile, 256 threads, 8x8 microtile, BK=16, double-buffered smem.
// Requires M%128==0, N%128==0, K%16==0.
#define ASTRIDE 132
__global__ void sgemm128(const float* __restrict__ A, const float* __restrict__ Bm,
                         const float* __restrict__ bias, float* __restrict__ Cm,
                         int M, int N, int K) {
    __shared__ float As[2][16][ASTRIDE];
    __shared__ float Bs[2][16][ASTRIDE];
    const int tid = threadIdx.x;
    const int row0 = blockIdx.y * 128;
    const int col0 = blockIdx.x * 128;
    const int ar = tid >> 2, ac = (tid & 3) << 2;     // A rows ar, ar+64; cols ac..ac+3
    const int br = tid >> 5, bc = (tid & 31) << 2;    // B rows br, br+8; cols bc..bc+3
    const int tx = tid & 15, ty = tid >> 4;
    const float* Ap = A + (size_t)(row0 + ar) * K;
    const float* Ap2 = Ap + (size_t)64 * K;

    float4 a0, a1, b0, b1;
    a0 = *(const float4*)(Ap + ac);
    a1 = *(const float4*)(Ap2 + ac);
    b0 = *(const float4*)(Bm + (size_t)br * N + col0 + bc);
    b1 = *(const float4*)(Bm + (size_t)(br + 8) * N + col0 + bc);
    As[0][ac + 0][ar] = a0.x; As[0][ac + 1][ar] = a0.y;
    As[0][ac + 2][ar] = a0.z; As[0][ac + 3][ar] = a0.w;
    As[0][ac + 0][ar + 64] = a1.x; As[0][ac + 1][ar + 64] = a1.y;
    As[0][ac + 2][ar + 64] = a1.z; As[0][ac + 3][ar + 64] = a1.w;
    *(float4*)&Bs[0][br][bc] = b0;
    *(float4*)&Bs[0][br + 8][bc] = b1;
    __syncthreads();

    float acc[8][8] = {};
    const int ntiles = K >> 4;
    int buf = 0;
    for (int kt = 0; kt < ntiles; kt++) {
        if (kt + 1 < ntiles) {
            const int k0 = (kt + 1) << 4;
            a0 = *(const float4*)(Ap + k0 + ac);
            a1 = *(const float4*)(Ap2 + k0 + ac);
            b0 = *(const float4*)(Bm + (size_t)(k0 + br) * N + col0 + bc);
            b1 = *(const float4*)(Bm + (size_t)(k0 + br + 8) * N + col0 + bc);
        }
#pragma unroll
        for (int kk = 0; kk < 16; kk++) {
            float a[8], b[8];
            *(float4*)(a)     = *(const float4*)&As[buf][kk][ty * 8];
            *(float4*)(a + 4) = *(const float4*)&As[buf][kk][ty * 8 + 4];
            *(float4*)(b)     = *(const float4*)&Bs[buf][kk][tx * 8];
            *(float4*)(b + 4) = *(const float4*)&Bs[buf][kk][tx * 8 + 4];
#pragma unroll
            for (int i = 0; i < 8; i++)
#pragma unroll
                for (int j = 0; j < 8; j++) acc[i][j] += a[i] * b[j];
        }
        if (kt + 1 < ntiles) {
            __syncthreads();
            const int nb = buf ^ 1;
            As[nb][ac + 0][ar] = a0.x; As[nb][ac + 1][ar] = a0.y;
            As[nb][ac + 2][ar] = a0.z; As[nb][ac + 3][ar] = a0.w;
            As[nb][ac + 0][ar + 64] = a1.x; As[nb][ac + 1][ar + 64] = a1.y;
            As[nb][ac + 2][ar + 64] = a1.z; As[nb][ac + 3][ar + 64] = a1.w;
            *(float4*)&Bs[nb][br][bc] = b0;
            *(float4*)&Bs[nb][br + 8][bc] = b1;
            __syncthreads();
            buf = nb;
        }
    }
    float bv[8];
    if (bias) {
        *(float4*)(bv)     = *(const float4*)&bias[col0 + tx * 8];
        *(float4*)(bv + 4) = *(const float4*)&bias[col0 + tx * 8 + 4];
    } else {
#pragma unroll
        for (int j = 0; j < 8; j++) bv[j] = 0.f;
    }
#pragma unroll
    for (int i = 0; i < 8; i++) {
        const int r = row0 + ty * 8 + i;
        float4 o0, o1;
        o0.x = acc[i][0] + bv[0]; o0.y = acc[i][1] + bv[1];
        o0.z = acc[i][2] + bv[2]; o0.w = acc[i][3] + bv[3];
        o1.x = acc[i][4] + bv[4]; o1.y = acc[i][5] + bv[5];
        o1.z = acc[i][6] + bv[6]; o1.w = acc[i][7] + bv[7];
        *(float4*)&Cm[(size_t)r * N + col0 + tx * 8] = o0;
        *(float4*)&Cm[(size_t)r * N + col0 + tx * 8 + 4] = o1;
    }
}

// ---------------- CSR build -------------------------------------------------
__global__ void zero_deg() {
    const int i = blockIdx.x * blockDim.x + threadIdx.x;
    if (i < NN) g_deg[i] = 0;
}
__global__ void hist_kernel(const int* __restrict__ ei) {
    const int e = blockIdx.x * blockDim.x + threadIdx.x;
    if (e >= EE) return;
    atomicAdd(&g_deg[ei[EE + e]], 1);
}
__global__ void scan_kernel() {
    __shared__ int sh[1024];
    const int t = threadIdx.x;
    int loc[32];
    int tot = 0;
    const int base = t * 32;
#pragma unroll
    for (int i = 0; i < 32; i++) { loc[i] = tot; tot += g_deg[base + i]; }
    sh[t] = tot;
    __syncthreads();
    for (int s = 1; s < 1024; s <<= 1) {
        const int v = (t >= s) ? sh[t - s] : 0;
        __syncthreads();
        sh[t] += v;
        __syncthreads();
    }
    const int ebase = sh[t] - tot;
#pragma unroll
    for (int i = 0; i < 32; i++) {
        g_off[base + i] = ebase + loc[i];
        g_cur[base + i] = ebase + loc[i];
    }
    if (t == 0) g_off[NN] = EE;
}
__global__ void scatter_kernel(const int* __restrict__ ei) {
    const int e = blockIdx.x * blockDim.x + threadIdx.x;
    if (e >= EE) return;
    const int d = ei[EE + e];
    const int p = atomicAdd(&g_cur[d], 1);
    g_csrc[p] = ei[e];
}

// ---------------- attention logits: es/ed per (node, head) -----------------
__global__ void esed_kernel(const float* __restrict__ hlin,
                            const float* __restrict__ a_src,
                            const float* __restrict__ a_dst,
                            float* __restrict__ es, float* __restrict__ ed) {
    const int w = (blockIdx.x * blockDim.x + threadIdx.x) >> 5;  // (n*H+h)
    const int lane = threadIdx.x & 31;
    if (w >= NN * HH) return;
    const int n = w >> 2, h = w & 3;
    const float* hp = hlin + (size_t)n * CC + h * FH;
    const float v0 = hp[lane], v1 = hp[lane + 32];
    float s = v0 * a_src[h * FH + lane] + v1 * a_src[h * FH + lane + 32];
    float d = v0 * a_dst[h * FH + lane] + v1 * a_dst[h * FH + lane + 32];
#pragma unroll
    for (int o = 16; o; o >>= 1) {
        s += __shfl_xor_sync(0xffffffffu, s, o);
        d += __shfl_xor_sync(0xffffffffu, d, o);
    }
    if (lane == 0) { es[w] = s; ed[w] = d; }
}

// ---------------- fused per-dst-node softmax (no atomics) -------------------
// warp per node: compute e for all in-edges + self loop, max, exp, denom.
// Stores ex (CSR order) in g_ex, 1/(den+eps) in g_dinv, self alpha in g_aself.
__global__ void att_softmax(const int* __restrict__ off, const int* __restrict__ csrc,
                            const float* __restrict__ es, const float* __restrict__ ed,
                            float* __restrict__ ex, float* __restrict__ dinv,
                            float* __restrict__ aself) {
    const int n = (blockIdx.x * blockDim.x + threadIdx.x) >> 5;
    const int lane = threadIdx.x & 31;
    if (n >= NN) return;
    const float4 edv = ((const float4*)ed)[n];
    const float4 esn = ((const float4*)es)[n];
    float4 esf;
    esf.x = leaky(esn.x + edv.x); esf.y = leaky(esn.y + edv.y);
    esf.z = leaky(esn.z + edv.z); esf.w = leaky(esn.w + edv.w);
    const int o0 = off[n], o1 = off[n + 1];
    float4 mx = esf;
    for (int i = o0 + lane; i < o1; i += 32) {
        const int s = csrc[i];
        const float4 ev = ((const float4*)es)[s];
        float4 e;
        e.x = leaky(ev.x + edv.x); e.y = leaky(ev.y + edv.y);
        e.z = leaky(ev.z + edv.z); e.w = leaky(ev.w + edv.w);
        ((float4*)ex)[i] = e;
        mx.x = fmaxf(mx.x, e.x); mx.y = fmaxf(mx.y, e.y);
        mx.z = fmaxf(mx.z, e.z); mx.w = fmaxf(mx.w, e.w);
    }
#pragma unroll
    for (int o = 16; o; o >>= 1) {
        mx.x = fmaxf(mx.x, __shfl_xor_sync(0xffffffffu, mx.x, o));
        mx.y = fmaxf(mx.y, __shfl_xor_sync(0xffffffffu, mx.y, o));
        mx.z = fmaxf(mx.z, __shfl_xor_sync(0xffffffffu, mx.z, o));
        mx.w = fmaxf(mx.w, __shfl_xor_sync(0xffffffffu, mx.w, o));
    }
    float4 xs;
    xs.x = __expf(esf.x - mx.x); xs.y = __expf(esf.y - mx.y);
    xs.z = __expf(esf.z - mx.z); xs.w = __expf(esf.w - mx.w);
    float4 sm;
    sm.x = (lane == 0) ? xs.x : 0.f; sm.y = (lane == 0) ? xs.y : 0.f;
    sm.z = (lane == 0) ? xs.z : 0.f; sm.w = (lane == 0) ? xs.w : 0.f;
    for (int i = o0 + lane; i < o1; i += 32) {
        float4 e = ((const float4*)ex)[i];
        float4 t;
        t.x = __expf(e.x - mx.x); t.y = __expf(e.y - mx.y);
        t.z = __expf(e.z - mx.z); t.w = __expf(e.w - mx.w);
        ((float4*)ex)[i] = t;
        sm.x += t.x; sm.y += t.y; sm.z += t.z; sm.w += t.w;
    }
#pragma unroll
    for (int o = 16; o; o >>= 1) {
        sm.x += __shfl_xor_sync(0xffffffffu, sm.x, o);
        sm.y += __shfl_xor_sync(0xffffffffu, sm.y, o);
        sm.z += __shfl_xor_sync(0xffffffffu, sm.z, o);
        sm.w += __shfl_xor_sync(0xffffffffu, sm.w, o);
    }
    if (lane == 0) {
        float4 iv;
        iv.x = 1.f / (sm.x + 1e-16f); iv.y = 1.f / (sm.y + 1e-16f);
        iv.z = 1.f / (sm.z + 1e-16f); iv.w = 1.f / (sm.w + 1e-16f);
        ((float4*)dinv)[n] = iv;
        float4 as;
        as.x = xs.x * iv.x; as.y = xs.y * iv.y;
        as.z = xs.z * iv.z; as.w = xs.w * iv.w;
        ((float4*)aself)[n] = as;
    }
}

// ---------------- fused aggregate + bias + ELU (no atomics) -----------------
// warp per dst node: acc = alpha_self*h[n] + sum alpha_e*h[s]; out = elu(acc+b)
__global__ void agg_csr(const int* __restrict__ off, const int* __restrict__ csrc,
                        const float* __restrict__ ex, const float* __restrict__ dinv,
                        const float* __restrict__ aself, const float* __restrict__ hlin,
                        const float* __restrict__ bias, float* __restrict__ out) {
    const int n = (blockIdx.x * blockDim.x + threadIdx.x) >> 5;
    const int lane = threadIdx.x & 31;
    if (n >= NN) return;
    const float4 dv = ((const float4*)dinv)[n];
    const float4 av = ((const float4*)aself)[n];
    const float di[4] = {dv.x, dv.y, dv.z, dv.w};
    const float asf[4] = {av.x, av.y, av.z, av.w};
    float acc[8];
    const float* hn = hlin + (size_t)n * CC;
#pragma unroll
    for (int j = 0; j < 8; j++) acc[j] = asf[j >> 1] * hn[lane + 32 * j];
    const int o0 = off[n], o1 = off[n + 1];
    int s_next = 0;
    float4 e_next = {0.f, 0.f, 0.f, 0.f};
    if (o0 < o1) { s_next = csrc[o0]; e_next = ((const float4*)ex)[o0]; }
    for (int i = o0; i < o1; i++) {
        const int s = s_next;
        const float4 e4 = e_next;
        if (i + 1 < o1) { s_next = csrc[i + 1]; e_next = ((const float4*)ex)[i + 1]; }
        const float al[4] = {e4.x * di[0], e4.y * di[1], e4.z * di[2], e4.w * di[3]};
        const float* hs = hlin + (size_t)s * CC;
#pragma unroll
        for (int j = 0; j < 8; j++) acc[j] += al[j >> 1] * hs[lane + 32 * j];
    }
#pragma unroll
    for (int j = 0; j < 8; j++) {
        const int c = lane + 32 * j;
        const float v = acc[j] + bias[c];
        out[(size_t)n * CC + c] = v > 0.f ? v : (__expf(v) - 1.f);
    }
}

// ---------------- pooling ---------------------------------------------------
__global__ void score_kernel(const float* __restrict__ X, const float* __restrict__ sw,
                             const float* __restrict__ sb, float* __restrict__ scores,
                             int rows) {
    const int w = (blockIdx.x * blockDim.x + threadIdx.x) >> 5;
    const int lane = threadIdx.x & 31;
    if (w >= rows) return;
    float s = 0.f;
#pragma unroll
    for (int c = lane; c < CC; c += 32) s += X[(size_t)w * CC + c] * sw[c];
#pragma unroll
    for (int o = 16; o; o >>= 1) s += __shfl_xor_sync(0xffffffffu, s, o);
    if (lane == 0) scores[w] = 1.f / (1.f + __expf(-(s + sb[0])));
}

template <int NPB, int KSEL>
__global__ void topk_kernel(const float* __restrict__ scores, int* __restrict__ idx_out) {
    __shared__ float sv[NPB];
    __shared__ int si[NPB];
    const int b = blockIdx.x, t = threadIdx.x;
    sv[t] = scores[b * NPB + t];
    si[t] = t;
    __syncthreads();
    for (int k = 2; k <= NPB; k <<= 1) {
        for (int j = k >> 1; j > 0; j >>= 1) {
            const int ixj = t ^ j;
            if (ixj > t) {
                const bool desc = ((t & k) == 0);
                const float a = sv[t], c = sv[ixj];
                if ((a < c) == desc) {
                    sv[t] = c; sv[ixj] = a;
                    const int tmp = si[t]; si[t] = si[ixj]; si[ixj] = tmp;
                }
            }
            __syncthreads();
        }
    }
    if (t < KSEL) idx_out[b * KSEL + t] = b * NPB + si[t];
}

__global__ void gather_kernel(const float* __restrict__ X, const int* __restrict__ idx,
                              float* __restrict__ out, int rows) {
    const int g = blockIdx.x * blockDim.x + threadIdx.x;
    if (g >= rows * 64) return;
    const int r = g >> 6, c4 = (g & 63) * 4;
    const float4 v = *reinterpret_cast<const float4*>(&X[(size_t)idx[r] * CC + c4]);
    *reinterpret_cast<float4*>(&out[(size_t)r * CC + c4]) = v;
}

// ---------------- readout ---------------------------------------------------
__global__ void mean_kernel(const float* __restrict__ X, float* __restrict__ g) {
    const int i = blockIdx.x * blockDim.x + threadIdx.x;
    if (i >= BB * CC) return;
    const int b = i >> 8, c = i & 255;
    float s = 0.f;
    for (int r = 0; r < K2; r++) s += X[(size_t)(b * K2 + r) * CC + c];
    g[i] = s * (1.f / K2);
}

__global__ void fc1_kernel(const float* __restrict__ g, const float* __restrict__ w,
                           const float* __restrict__ bias, float* __restrict__ out) {
    const int i = blockIdx.x * blockDim.x + threadIdx.x;
    if (i >= BB * 64) return;
    const int b = i >> 6, o = i & 63;
    float s = bias[o];
    for (int k = 0; k < CC; k++) s += g[b * CC + k] * w[k * 64 + o];
    out[i] = s > 0.f ? s : 0.f;
}

__global__ void fc2_lsm_kernel(const float* __restrict__ f, const float* __restrict__ w,
                               const float* __restrict__ bias, float* __restrict__ out) {
    const int b = threadIdx.x;
    if (b >= BB) return;
    float l0 = bias[0], l1 = bias[1];
    for (int k = 0; k < 64; k++) {
        const float v = f[b * 64 + k];
        l0 += v * w[k * 2 + 0];
        l1 += v * w[k * 2 + 1];
    }
    const float mm = fmaxf(l0, l1);
    const float lse = mm + logf(__expf(l0 - mm) + __expf(l1 - mm));
    out[b * 2 + 0] = l0 - lse;
    out[b * 2 + 1] = l1 - lse;
}

// ---------------- host orchestration ----------------------------------------
static float* sym(const void* s) {
    void* p = nullptr;
    cudaGetSymbolAddress(&p, (const void*)s);
    return (float*)p;
}

extern "C" void kernel_launch(void* const* d_in, const int* in_sizes, int n_in,
                              void* d_out, int out_size) {
    const float* x      = (const float*)d_in[0];
    const int*   ei     = (const int*)  d_in[1];
    const float* W1     = (const float*)d_in[3];
    const float* asrc1  = (const float*)d_in[4];
    const float* adst1  = (const float*)d_in[5];
    const float* b1     = (const float*)d_in[6];
    const float* W2     = (const float*)d_in[7];
    const float* asrc2  = (const float*)d_in[8];
    const float* adst2  = (const float*)d_in[9];
    const float* b2     = (const float*)d_in[10];
    const float* p1_sw  = (const float*)d_in[11];
    const float* p1_sb  = (const float*)d_in[12];
    const float* p1_tw  = (const float*)d_in[13];
    const float* p1_tb  = (const float*)d_in[14];
    const float* p2_sw  = (const float*)d_in[15];
    const float* p2_sb  = (const float*)d_in[16];
    const float* p2_tw  = (const float*)d_in[17];
    const float* p2_tb  = (const float*)d_in[18];
    const float* c1w    = (const float*)d_in[19];
    const float* c1b    = (const float*)d_in[20];
    const float* c2w    = (const float*)d_in[21];
    const float* c2b    = (const float*)d_in[22];
    float* out = (float*)d_out;

    float*    hlin  = sym(g_hlin);
    float*    hout  = sym(g_hout);
    float*    es    = sym(g_es);
    float*    ed    = sym(g_ed);
    float*    dinv  = sym(g_dinv);
    float*    aself = sym(g_aself);
    float*    ex    = sym(g_ex);
    int*      off   = (int*)sym(g_off);
    int*      csrc  = (int*)sym(g_csrc);
    float*    selb  = sym(g_sel);
    float*    pool1 = sym(g_pool1);
    float*    pool2 = sym(g_pool2);
    int*      idx   = (int*)sym(g_idx);
    float*    sc    = sym(g_scores);
    float*    gmean = sym(g_gmean);
    float*    fc1   = sym(g_fc1);

    dim3 t256(256);

    // ---- CSR build (graph shared by both layers) ----
    zero_deg<<<NN / 256, t256>>>();
    hist_kernel<<<EE / 256, t256>>>(ei);
    scan_kernel<<<1, 1024>>>();
    scatter_kernel<<<EE / 256, t256>>>(ei);

    // ---- GAT layer 1 ----
    sgemm128<<<dim3(CC / 128, NN / 128), t256>>>(x, W1, nullptr, hlin, NN, CC, FIN);
    esed_kernel<<<(NN * HH) / 8, t256>>>(hlin, asrc1, adst1, es, ed);
    att_softmax<<<(NN * 32) / 256, t256>>>(off, csrc, es, ed, ex, dinv, aself);
    agg_csr<<<(NN * 32) / 256, t256>>>(off, csrc, ex, dinv, aself, hlin, b1, hout);

    // ---- GAT layer 2 ----
    sgemm128<<<dim3(CC / 128, NN / 128), t256>>>(hout, W2, nullptr, hlin, NN, CC, CC);
    esed_kernel<<<(NN * HH) / 8, t256>>>(hlin, asrc2, adst2, es, ed);
    att_softmax<<<(NN * 32) / 256, t256>>>(off, csrc, es, ed, ex, dinv, aself);
    agg_csr<<<(NN * 32) / 256, t256>>>(off, csrc, ex, dinv, aself, hlin, b2, hout);

    // ---- Pool 1 (top-256 of 512 per graph) ----
    score_kernel<<<(NN * 32) / 256, t256>>>(hout, p1_sw, p1_sb, sc, NN);
    topk_kernel<NPG, K1><<<BB, NPG>>>(sc, idx);
    gather_kernel<<<(BB * K1 * 64) / 256, t256>>>(hout, idx, selb, BB * K1);
    sgemm128<<<dim3(CC / 128, (BB * K1) / 128), t256>>>(selb, p1_tw, p1_tb, pool1, BB * K1, CC, CC);

    // ---- Pool 2 (top-128 of 256 per graph) ----
    score_kernel<<<(BB * K1 * 32) / 256, t256>>>(pool1, p2_sw, p2_sb, sc, BB * K1);
    topk_kernel<K1, K2><<<BB, K1>>>(sc, idx);
    gather_kernel<<<(BB * K2 * 64) / 256, t256>>>(pool1, idx, selb, BB * K2);
    sgemm128<<<dim3(CC / 128, (BB * K2) / 128), t256>>>(selb, p2_tw, p2_tb, pool2, BB * K2, CC, CC);

    // ---- readout ----
    mean_kernel<<<(BB * CC) / 256, t256>>>(pool2, gmean);
    fc1_kernel<<<(BB * 64) / 256, t256>>>(gmean, c1w, c1b, fc1);
    fc2_lsm_kernel<<<1, 64>>>(fc1, c2w, c2b, out);
}

// round 3
// speedup vs baseline: 1.4792x; 1.1670x over previous
#include <cuda_runtime.h>
#include <cuda_bf16.h>

// Problem constants
#define NN   32768
#define FIN  128
#define CC   256
#define HH   4
#define FH   64
#define EE   524288
#define BB   64
#define NPG  512
#define K1   256
#define K2   128

// ---------------- scratch (device globals; no allocation allowed) ----------
__device__ float    g_hlin[NN * CC];
__device__ float    g_hout[NN * CC];
__device__ float    g_es[NN * HH];
__device__ float    g_ed[NN * HH];
__device__ float    g_dinv[NN * HH];
__device__ float    g_aself[NN * HH];
__device__ float    g_ex[EE * HH];
__device__ int      g_deg[NN];
__device__ int      g_off[NN + 1];
__device__ int      g_cur[NN];
__device__ int      g_csrc[EE];
__device__ float    g_sel[(BB * K1) * CC];
__device__ float    g_pool1[(BB * K1) * CC];
__device__ float    g_pool2[(BB * K2) * CC];
__device__ int      g_idx[BB * K1];
__device__ float    g_scores[NN];
__device__ float    g_gmean[BB * CC];
__device__ float    g_fc1[BB * 64];

__device__ __forceinline__ float leaky(float x) { return x > 0.f ? x : 0.2f * x; }

// ---------------- packed f32x2 helpers (sm_103a FFMA2) ----------------------
__device__ __forceinline__ void ffma2(unsigned long long& d, unsigned long long a,
                                      unsigned long long b) {
    asm("fma.rn.f32x2 %0, %1, %2, %0;" : "+l"(d) : "l"(a), "l"(b));
}
__device__ __forceinline__ unsigned long long pack2(float x, float y) {
    unsigned long long r;
    asm("mov.b64 %0, {%1, %2};" : "=l"(r) : "f"(x), "f"(y));
    return r;
}
__device__ __forceinline__ float2 unpack2(unsigned long long v) {
    float2 r;
    asm("mov.b64 {%0, %1}, %2;" : "=f"(r.x), "=f"(r.y) : "l"(v));
    return r;
}

// ---------------- SGEMM: C[M,N] = A[M,K] @ B[K,N] (+bias), fp32 ------------
// 128x128 tile, 256 threads, 8x8 microtile via packed FFMA2, BK=16,
// double-buffered smem. Requires M%128==0, N%128==0, K%16==0.
#define ASTRIDE 132
__global__ void __launch_bounds__(256, 2)
sgemm128(const float* __restrict__ A, const float* __restrict__ Bm,
         const float* __restrict__ bias, float* __restrict__ Cm,
         int M, int N, int K) {
    __shared__ float As[2][16][ASTRIDE];
    __shared__ float Bs[2][16][ASTRIDE];
    const int tid = threadIdx.x;
    const int row0 = blockIdx.y * 128;
    const int col0 = blockIdx.x * 128;
    const int ar = tid >> 2, ac = (tid & 3) << 2;
    const int br = tid >> 5, bc = (tid & 31) << 2;
    const int tx = tid & 15, ty = tid >> 4;
    const float* Ap = A + (size_t)(row0 + ar) * K;
    const float* Ap2 = Ap + (size_t)64 * K;

    float4 a0, a1, b0, b1;
    a0 = *(const float4*)(Ap + ac);
    a1 = *(const float4*)(Ap2 + ac);
    b0 = *(const float4*)(Bm + (size_t)br * N + col0 + bc);
    b1 = *(const float4*)(Bm + (size_t)(br + 8) * N + col0 + bc);
    As[0][ac + 0][ar] = a0.x; As[0][ac + 1][ar] = a0.y;
    As[0][ac + 2][ar] = a0.z; As[0][ac + 3][ar] = a0.w;
    As[0][ac + 0][ar + 64] = a1.x; As[0][ac + 1][ar + 64] = a1.y;
    As[0][ac + 2][ar + 64] = a1.z; As[0][ac + 3][ar + 64] = a1.w;
    *(float4*)&Bs[0][br][bc] = b0;
    *(float4*)&Bs[0][br + 8][bc] = b1;
    __syncthreads();

    unsigned long long acc2[8][4];
#pragma unroll
    for (int i = 0; i < 8; i++)
#pragma unroll
        for (int j = 0; j < 4; j++) acc2[i][j] = 0ull;

    const int ntiles = K >> 4;
    int buf = 0;
    for (int kt = 0; kt < ntiles; kt++) {
        if (kt + 1 < ntiles) {
            const int k0 = (kt + 1) << 4;
            a0 = *(const float4*)(Ap + k0 + ac);
            a1 = *(const float4*)(Ap2 + k0 + ac);
            b0 = *(const float4*)(Bm + (size_t)(k0 + br) * N + col0 + bc);
            b1 = *(const float4*)(Bm + (size_t)(k0 + br + 8) * N + col0 + bc);
        }
#pragma unroll
        for (int kk = 0; kk < 16; kk++) {
            float a[8], b[8];
            *(float4*)(a)     = *(const float4*)&As[buf][kk][ty * 8];
            *(float4*)(a + 4) = *(const float4*)&As[buf][kk][ty * 8 + 4];
            *(float4*)(b)     = *(const float4*)&Bs[buf][kk][tx * 8];
            *(float4*)(b + 4) = *(const float4*)&Bs[buf][kk][tx * 8 + 4];
            unsigned long long bp[4];
            bp[0] = pack2(b[0], b[1]); bp[1] = pack2(b[2], b[3]);
            bp[2] = pack2(b[4], b[5]); bp[3] = pack2(b[6], b[7]);
#pragma unroll
            for (int i = 0; i < 8; i++) {
                const unsigned long long ad = pack2(a[i], a[i]);
                ffma2(acc2[i][0], ad, bp[0]);
                ffma2(acc2[i][1], ad, bp[1]);
                ffma2(acc2[i][2], ad, bp[2]);
                ffma2(acc2[i][3], ad, bp[3]);
            }
        }
        if (kt + 1 < ntiles) {
            __syncthreads();
            const int nb = buf ^ 1;
            As[nb][ac + 0][ar] = a0.x; As[nb][ac + 1][ar] = a0.y;
            As[nb][ac + 2][ar] = a0.z; As[nb][ac + 3][ar] = a0.w;
            As[nb][ac + 0][ar + 64] = a1.x; As[nb][ac + 1][ar + 64] = a1.y;
            As[nb][ac + 2][ar + 64] = a1.z; As[nb][ac + 3][ar + 64] = a1.w;
            *(float4*)&Bs[nb][br][bc] = b0;
            *(float4*)&Bs[nb][br + 8][bc] = b1;
            __syncthreads();
            buf = nb;
        }
    }
    float bv[8];
    if (bias) {
        *(float4*)(bv)     = *(const float4*)&bias[col0 + tx * 8];
        *(float4*)(bv + 4) = *(const float4*)&bias[col0 + tx * 8 + 4];
    } else {
#pragma unroll
        for (int j = 0; j < 8; j++) bv[j] = 0.f;
    }
#pragma unroll
    for (int i = 0; i < 8; i++) {
        const int r = row0 + ty * 8 + i;
        const float2 c0 = unpack2(acc2[i][0]);
        const float2 c1 = unpack2(acc2[i][1]);
        const float2 c2 = unpack2(acc2[i][2]);
        const float2 c3 = unpack2(acc2[i][3]);
        float4 o0, o1;
        o0.x = c0.x + bv[0]; o0.y = c0.y + bv[1];
        o0.z = c1.x + bv[2]; o0.w = c1.y + bv[3];
        o1.x = c2.x + bv[4]; o1.y = c2.y + bv[5];
        o1.z = c3.x + bv[6]; o1.w = c3.y + bv[7];
        *(float4*)&Cm[(size_t)r * N + col0 + tx * 8] = o0;
        *(float4*)&Cm[(size_t)r * N + col0 + tx * 8 + 4] = o1;
    }
}

// ---------------- CSR build -------------------------------------------------
__global__ void zero_deg() {
    const int i = blockIdx.x * blockDim.x + threadIdx.x;
    if (i < NN) g_deg[i] = 0;
}
__global__ void hist_kernel(const int* __restrict__ ei) {
    const int e = blockIdx.x * blockDim.x + threadIdx.x;
    if (e >= EE) return;
    atomicAdd(&g_deg[ei[EE + e]], 1);
}
__global__ void scan_kernel() {
    __shared__ int sh[1024];
    const int t = threadIdx.x;
    int loc[32];
    int tot = 0;
    const int base = t * 32;
#pragma unroll
    for (int i = 0; i < 32; i++) { loc[i] = tot; tot += g_deg[base + i]; }
    sh[t] = tot;
    __syncthreads();
    for (int s = 1; s < 1024; s <<= 1) {
        const int v = (t >= s) ? sh[t - s] : 0;
        __syncthreads();
        sh[t] += v;
        __syncthreads();
    }
    const int ebase = sh[t] - tot;
#pragma unroll
    for (int i = 0; i < 32; i++) {
        g_off[base + i] = ebase + loc[i];
        g_cur[base + i] = ebase + loc[i];
    }
    if (t == 0) g_off[NN] = EE;
}
__global__ void scatter_kernel(const int* __restrict__ ei) {
    const int e = blockIdx.x * blockDim.x + threadIdx.x;
    if (e >= EE) return;
    const int d = ei[EE + e];
    const int p = atomicAdd(&g_cur[d], 1);
    g_csrc[p] = ei[e];
}

// ---------------- attention logits: es/ed per (node, head) -----------------
__global__ void esed_kernel(const float* __restrict__ hlin,
                            const float* __restrict__ a_src,
                            const float* __restrict__ a_dst,
                            float* __restrict__ es, float* __restrict__ ed) {
    const int w = (blockIdx.x * blockDim.x + threadIdx.x) >> 5;  // (n*H+h)
    const int lane = threadIdx.x & 31;
    if (w >= NN * HH) return;
    const int n = w >> 2, h = w & 3;
    const float* hp = hlin + (size_t)n * CC + h * FH;
    const float v0 = hp[lane], v1 = hp[lane + 32];
    float s = v0 * a_src[h * FH + lane] + v1 * a_src[h * FH + lane + 32];
    float d = v0 * a_dst[h * FH + lane] + v1 * a_dst[h * FH + lane + 32];
#pragma unroll
    for (int o = 16; o; o >>= 1) {
        s += __shfl_xor_sync(0xffffffffu, s, o);
        d += __shfl_xor_sync(0xffffffffu, d, o);
    }
    if (lane == 0) { es[w] = s; ed[w] = d; }
}

// ---------------- fused per-dst-node softmax (no atomics) -------------------
__global__ void att_softmax(const int* __restrict__ off, const int* __restrict__ csrc,
                            const float* __restrict__ es, const float* __restrict__ ed,
                            float* __restrict__ ex, float* __restrict__ dinv,
                            float* __restrict__ aself) {
    const int n = (blockIdx.x * blockDim.x + threadIdx.x) >> 5;
    const int lane = threadIdx.x & 31;
    if (n >= NN) return;
    const float4 edv = ((const float4*)ed)[n];
    const float4 esn = ((const float4*)es)[n];
    float4 esf;
    esf.x = leaky(esn.x + edv.x); esf.y = leaky(esn.y + edv.y);
    esf.z = leaky(esn.z + edv.z); esf.w = leaky(esn.w + edv.w);
    const int o0 = off[n], o1 = off[n + 1];
    float4 mx = esf;
    for (int i = o0 + lane; i < o1; i += 32) {
        const int s = csrc[i];
        const float4 ev = ((const float4*)es)[s];
        float4 e;
        e.x = leaky(ev.x + edv.x); e.y = leaky(ev.y + edv.y);
        e.z = leaky(ev.z + edv.z); e.w = leaky(ev.w + edv.w);
        ((float4*)ex)[i] = e;
        mx.x = fmaxf(mx.x, e.x); mx.y = fmaxf(mx.y, e.y);
        mx.z = fmaxf(mx.z, e.z); mx.w = fmaxf(mx.w, e.w);
    }
#pragma unroll
    for (int o = 16; o; o >>= 1) {
        mx.x = fmaxf(mx.x, __shfl_xor_sync(0xffffffffu, mx.x, o));
        mx.y = fmaxf(mx.y, __shfl_xor_sync(0xffffffffu, mx.y, o));
        mx.z = fmaxf(mx.z, __shfl_xor_sync(0xffffffffu, mx.z, o));
        mx.w = fmaxf(mx.w, __shfl_xor_sync(0xffffffffu, mx.w, o));
    }
    float4 xs;
    xs.x = __expf(esf.x - mx.x); xs.y = __expf(esf.y - mx.y);
    xs.z = __expf(esf.z - mx.z); xs.w = __expf(esf.w - mx.w);
    float4 sm;
    sm.x = (lane == 0) ? xs.x : 0.f; sm.y = (lane == 0) ? xs.y : 0.f;
    sm.z = (lane == 0) ? xs.z : 0.f; sm.w = (lane == 0) ? xs.w : 0.f;
    for (int i = o0 + lane; i < o1; i += 32) {
        float4 e = ((const float4*)ex)[i];
        float4 t;
        t.x = __expf(e.x - mx.x); t.y = __expf(e.y - mx.y);
        t.z = __expf(e.z - mx.z); t.w = __expf(e.w - mx.w);
        ((float4*)ex)[i] = t;
        sm.x += t.x; sm.y += t.y; sm.z += t.z; sm.w += t.w;
    }
#pragma unroll
    for (int o = 16; o; o >>= 1) {
        sm.x += __shfl_xor_sync(0xffffffffu, sm.x, o);
        sm.y += __shfl_xor_sync(0xffffffffu, sm.y, o);
        sm.z += __shfl_xor_sync(0xffffffffu, sm.z, o);
        sm.w += __shfl_xor_sync(0xffffffffu, sm.w, o);
    }
    if (lane == 0) {
        float4 iv;
        iv.x = 1.f / (sm.x + 1e-16f); iv.y = 1.f / (sm.y + 1e-16f);
        iv.z = 1.f / (sm.z + 1e-16f); iv.w = 1.f / (sm.w + 1e-16f);
        ((float4*)dinv)[n] = iv;
        float4 as;
        as.x = xs.x * iv.x; as.y = xs.y * iv.y;
        as.z = xs.z * iv.z; as.w = xs.w * iv.w;
        ((float4*)aself)[n] = as;
    }
}

// ---------------- fused aggregate + bias + ELU (no atomics) -----------------
__global__ void agg_csr(const int* __restrict__ off, const int* __restrict__ csrc,
                        const float* __restrict__ ex, const float* __restrict__ dinv,
                        const float* __restrict__ aself, const float* __restrict__ hlin,
                        const float* __restrict__ bias, float* __restrict__ out) {
    const int n = (blockIdx.x * blockDim.x + threadIdx.x) >> 5;
    const int lane = threadIdx.x & 31;
    if (n >= NN) return;
    const float4 dv = ((const float4*)dinv)[n];
    const float4 av = ((const float4*)aself)[n];
    const float di[4] = {dv.x, dv.y, dv.z, dv.w};
    const float asf[4] = {av.x, av.y, av.z, av.w};
    float acc[8];
    const float* hn = hlin + (size_t)n * CC;
#pragma unroll
    for (int j = 0; j < 8; j++) acc[j] = asf[j >> 1] * hn[lane + 32 * j];
    const int o0 = off[n], o1 = off[n + 1];
    int s_next = 0;
    float4 e_next = {0.f, 0.f, 0.f, 0.f};
    if (o0 < o1) { s_next = csrc[o0]; e_next = ((const float4*)ex)[o0]; }
    for (int i = o0; i < o1; i++) {
        const int s = s_next;
        const float4 e4 = e_next;
        if (i + 1 < o1) { s_next = csrc[i + 1]; e_next = ((const float4*)ex)[i + 1]; }
        const float al[4] = {e4.x * di[0], e4.y * di[1], e4.z * di[2], e4.w * di[3]};
        const float* hs = hlin + (size_t)s * CC;
#pragma unroll
        for (int j = 0; j < 8; j++) acc[j] += al[j >> 1] * hs[lane + 32 * j];
    }
#pragma unroll
    for (int j = 0; j < 8; j++) {
        const int c = lane + 32 * j;
        const float v = acc[j] + bias[c];
        out[(size_t)n * CC + c] = v > 0.f ? v : (__expf(v) - 1.f);
    }
}

// ---------------- pooling ---------------------------------------------------
__global__ void score_kernel(const float* __restrict__ X, const float* __restrict__ sw,
                             const float* __restrict__ sb, float* __restrict__ scores,
                             int rows) {
    const int w = (blockIdx.x * blockDim.x + threadIdx.x) >> 5;
    const int lane = threadIdx.x & 31;
    if (w >= rows) return;
    float s = 0.f;
#pragma unroll
    for (int c = lane; c < CC; c += 32) s += X[(size_t)w * CC + c] * sw[c];
#pragma unroll
    for (int o = 16; o; o >>= 1) s += __shfl_xor_sync(0xffffffffu, s, o);
    if (lane == 0) scores[w] = 1.f / (1.f + __expf(-(s + sb[0])));
}

template <int NPB, int KSEL>
__global__ void topk_kernel(const float* __restrict__ scores, int* __restrict__ idx_out) {
    __shared__ float sv[NPB];
    __shared__ int si[NPB];
    const int b = blockIdx.x, t = threadIdx.x;
    sv[t] = scores[b * NPB + t];
    si[t] = t;
    __syncthreads();
    for (int k = 2; k <= NPB; k <<= 1) {
        for (int j = k >> 1; j > 0; j >>= 1) {
            const int ixj = t ^ j;
            if (ixj > t) {
                const bool desc = ((t & k) == 0);
                const float a = sv[t], c = sv[ixj];
                if ((a < c) == desc) {
                    sv[t] = c; sv[ixj] = a;
                    const int tmp = si[t]; si[t] = si[ixj]; si[ixj] = tmp;
                }
            }
            __syncthreads();
        }
    }
    if (t < KSEL) idx_out[b * KSEL + t] = b * NPB + si[t];
}

__global__ void gather_kernel(const float* __restrict__ X, const int* __restrict__ idx,
                              float* __restrict__ out, int rows) {
    const int g = blockIdx.x * blockDim.x + threadIdx.x;
    if (g >= rows * 64) return;
    const int r = g >> 6, c4 = (g & 63) * 4;
    const float4 v = *reinterpret_cast<const float4*>(&X[(size_t)idx[r] * CC + c4]);
    *reinterpret_cast<float4*>(&out[(size_t)r * CC + c4]) = v;
}

// ---------------- readout ---------------------------------------------------
__global__ void mean_kernel(const float* __restrict__ X, float* __restrict__ g) {
    const int i = blockIdx.x * blockDim.x + threadIdx.x;
    if (i >= BB * CC) return;
    const int b = i >> 8, c = i & 255;
    float s = 0.f;
    for (int r = 0; r < K2; r++) s += X[(size_t)(b * K2 + r) * CC + c];
    g[i] = s * (1.f / K2);
}

__global__ void fc1_kernel(const float* __restrict__ g, const float* __restrict__ w,
                           const float* __restrict__ bias, float* __restrict__ out) {
    const int i = blockIdx.x * blockDim.x + threadIdx.x;
    if (i >= BB * 64) return;
    const int b = i >> 6, o = i & 63;
    float s = bias[o];
    for (int k = 0; k < CC; k++) s += g[b * CC + k] * w[k * 64 + o];
    out[i] = s > 0.f ? s : 0.f;
}

__global__ void fc2_lsm_kernel(const float* __restrict__ f, const float* __restrict__ w,
                               const float* __restrict__ bias, float* __restrict__ out) {
    const int b = threadIdx.x;
    if (b >= BB) return;
    float l0 = bias[0], l1 = bias[1];
    for (int k = 0; k < 64; k++) {
        const float v = f[b * 64 + k];
        l0 += v * w[k * 2 + 0];
        l1 += v * w[k * 2 + 1];
    }
    const float mm = fmaxf(l0, l1);
    const float lse = mm + logf(__expf(l0 - mm) + __expf(l1 - mm));
    out[b * 2 + 0] = l0 - lse;
    out[b * 2 + 1] = l1 - lse;
}

// ---------------- host orchestration ----------------------------------------
static float* sym(const void* s) {
    void* p = nullptr;
    cudaGetSymbolAddress(&p, (const void*)s);
    return (float*)p;
}

extern "C" void kernel_launch(void* const* d_in, const int* in_sizes, int n_in,
                              void* d_out, int out_size) {
    const float* x      = (const float*)d_in[0];
    const int*   ei     = (const int*)  d_in[1];
    const float* W1     = (const float*)d_in[3];
    const float* asrc1  = (const float*)d_in[4];
    const float* adst1  = (const float*)d_in[5];
    const float* b1     = (const float*)d_in[6];
    const float* W2     = (const float*)d_in[7];
    const float* asrc2  = (const float*)d_in[8];
    const float* adst2  = (const float*)d_in[9];
    const float* b2     = (const float*)d_in[10];
    const float* p1_sw  = (const float*)d_in[11];
    const float* p1_sb  = (const float*)d_in[12];
    const float* p1_tw  = (const float*)d_in[13];
    const float* p1_tb  = (const float*)d_in[14];
    const float* p2_sw  = (const float*)d_in[15];
    const float* p2_sb  = (const float*)d_in[16];
    const float* p2_tw  = (const float*)d_in[17];
    const float* p2_tb  = (const float*)d_in[18];
    const float* c1w    = (const float*)d_in[19];
    const float* c1b    = (const float*)d_in[20];
    const float* c2w    = (const float*)d_in[21];
    const float* c2b    = (const float*)d_in[22];
    float* out = (float*)d_out;

    float*    hlin  = sym(g_hlin);
    float*    hout  = sym(g_hout);
    float*    es    = sym(g_es);
    float*    ed    = sym(g_ed);
    float*    dinv  = sym(g_dinv);
    float*    aself = sym(g_aself);
    float*    ex    = sym(g_ex);
    int*      off   = (int*)sym(g_off);
    int*      csrc  = (int*)sym(g_csrc);
    float*    selb  = sym(g_sel);
    float*    pool1 = sym(g_pool1);
    float*    pool2 = sym(g_pool2);
    int*      idx   = (int*)sym(g_idx);
    float*    sc    = sym(g_scores);
    float*    gmean = sym(g_gmean);
    float*    fc1   = sym(g_fc1);

    dim3 t256(256);

    // ---- CSR build (graph shared by both layers) ----
    zero_deg<<<NN / 256, t256>>>();
    hist_kernel<<<EE / 256, t256>>>(ei);
    scan_kernel<<<1, 1024>>>();
    scatter_kernel<<<EE / 256, t256>>>(ei);

    // ---- GAT layer 1 ----
    sgemm128<<<dim3(CC / 128, NN / 128), t256>>>(x, W1, nullptr, hlin, NN, CC, FIN);
    esed_kernel<<<(NN * HH) / 8, t256>>>(hlin, asrc1, adst1, es, ed);
    att_softmax<<<(NN * 32) / 256, t256>>>(off, csrc, es, ed, ex, dinv, aself);
    agg_csr<<<(NN * 32) / 256, t256>>>(off, csrc, ex, dinv, aself, hlin, b1, hout);

    // ---- GAT layer 2 ----
    sgemm128<<<dim3(CC / 128, NN / 128), t256>>>(hout, W2, nullptr, hlin, NN, CC, CC);
    esed_kernel<<<(NN * HH) / 8, t256>>>(hlin, asrc2, adst2, es, ed);
    att_softmax<<<(NN * 32) / 256, t256>>>(off, csrc, es, ed, ex, dinv, aself);
    agg_csr<<<(NN * 32) / 256, t256>>>(off, csrc, ex, dinv, aself, hlin, b2, hout);

    // ---- Pool 1 (top-256 of 512 per graph) ----
    score_kernel<<<(NN * 32) / 256, t256>>>(hout, p1_sw, p1_sb, sc, NN);
    topk_kernel<NPG, K1><<<BB, NPG>>>(sc, idx);
    gather_kernel<<<(BB * K1 * 64) / 256, t256>>>(hout, idx, selb, BB * K1);
    sgemm128<<<dim3(CC / 128, (BB * K1) / 128), t256>>>(selb, p1_tw, p1_tb, pool1, BB * K1, CC, CC);

    // ---- Pool 2 (top-128 of 256 per graph) ----
    score_kernel<<<(BB * K1 * 32) / 256, t256>>>(pool1, p2_sw, p2_sb, sc, BB * K1);
    topk_kernel<K1, K2><<<BB, K1>>>(sc, idx);
    gather_kernel<<<(BB * K2 * 64) / 256, t256>>>(pool1, idx, selb, BB * K2);
    sgemm128<<<dim3(CC / 128, (BB * K2) / 128), t256>>>(selb, p2_tw, p2_tb, pool2, BB * K2, CC, CC);

    // ---- readout ----
    mean_kernel<<<(BB * CC) / 256, t256>>>(pool2, gmean);
    fc1_kernel<<<(BB * 64) / 256, t256>>>(gmean, c1w, c1b, fc1);
    fc2_lsm_kernel<<<1, 64>>>(fc1, c2w, c2b, out);
}